// round 1
// baseline (speedup 1.0000x reference)
#include <cuda_runtime.h>
#include <cstdint>

#define Bsz 2048
#define Tlen 512
#define Ktag 32
#define FULLMASK 0xFFFFFFFFu

// Scratch: backpointers packed 4 timesteps per uint32 (bp fits in a byte).
// Layout: g_bp[(t>>2) * (B*K) + b*K + j]  -> coalesced 128B per-warp stores.
__device__ uint32_t g_bp[(Tlen / 4) * Bsz * Ktag];   // ~33.5 MB, stays in L2
__device__ int      g_lastTag[Bsz];
__device__ float    g_logNorm[Bsz];

// ---------------------------------------------------------------------------
// Kernel 1: forward passes. Warp w < B  -> Viterbi for batch w.
//           Warp w in [B, 2B)          -> logsumexp forward for batch w-B.
// One warp per batch element; lane j owns tag j.
// ---------------------------------------------------------------------------
__global__ __launch_bounds__(128, 7)
void crf_forward(const float* __restrict__ pot,
                 const float* __restrict__ trans,
                 const int*   __restrict__ slen,
                 float*       __restrict__ out)
{
    const int warp = (blockIdx.x * blockDim.x + threadIdx.x) >> 5;
    const int j    = threadIdx.x & 31;

    if (warp < Bsz) {
        // ----------------------- Viterbi -----------------------
        const int b = warp;
        float Tcol[32];
#pragma unroll
        for (int i = 0; i < 32; ++i) Tcol[i] = __ldg(&trans[i * 32 + j]);

        const float* p = pot + (size_t)b * Tlen * Ktag + j;
        const int L = slen[b];

        float alpha = __ldg(p);          // t = 0
        uint32_t bpw = 0;

#pragma unroll 4
        for (int t = 1; t < L; ++t) {
            const float pc = __ldg(p + t * Ktag);   // prefetch early, used at end

            // 4 index-ordered chains, strict-> update preserves first-argmax.
            float bv0 = -3.4e38f, bv1 = -3.4e38f, bv2 = -3.4e38f, bv3 = -3.4e38f;
            int   bi0 = 0, bi1 = 8, bi2 = 16, bi3 = 24;
#pragma unroll
            for (int r = 0; r < 8; ++r) {
                float a, s;
                a = __shfl_sync(FULLMASK, alpha, r);
                s = a + Tcol[r];
                if (s > bv0) { bv0 = s; bi0 = r; }
                a = __shfl_sync(FULLMASK, alpha, 8 + r);
                s = a + Tcol[8 + r];
                if (s > bv1) { bv1 = s; bi1 = 8 + r; }
                a = __shfl_sync(FULLMASK, alpha, 16 + r);
                s = a + Tcol[16 + r];
                if (s > bv2) { bv2 = s; bi2 = 16 + r; }
                a = __shfl_sync(FULLMASK, alpha, 24 + r);
                s = a + Tcol[24 + r];
                if (s > bv3) { bv3 = s; bi3 = 24 + r; }
            }
            if (bv1 > bv0) { bv0 = bv1; bi0 = bi1; }
            if (bv2 > bv0) { bv0 = bv2; bi0 = bi2; }
            if (bv3 > bv0) { bv0 = bv3; bi0 = bi3; }

            alpha = pc + bv0;
            bpw |= (uint32_t)bi0 << ((t & 3) * 8);
            if ((t & 3) == 3) {
                g_bp[(t >> 2) * (Bsz * Ktag) + b * Ktag + j] = bpw;
                bpw = 0;
            }
        }
        if (L >= 2 && ((L - 1) & 3) != 3)
            g_bp[((L - 1) >> 2) * (Bsz * Ktag) + b * Ktag + j] = bpw;

        // final max/argmax over alpha (first-max semantics)
        float v = alpha;
        int idx = j;
#pragma unroll
        for (int off = 16; off; off >>= 1) {
            float vv = __shfl_xor_sync(FULLMASK, v, off);
            int   ii = __shfl_xor_sync(FULLMASK, idx, off);
            if (vv > v || (vv == v && ii < idx)) { v = vv; idx = ii; }
        }
        if (j == 0) {
            out[(size_t)Bsz * Tlen + b] = v;   // best_score
            g_lastTag[b] = idx;
        }
    } else if (warp < 2 * Bsz) {
        // ----------------------- logsumexp forward -----------------------
        const int b = warp - Bsz;
        float Ecol[32];
#pragma unroll
        for (int i = 0; i < 32; ++i) Ecol[i] = expf(__ldg(&trans[i * 32 + j]));

        const float* p = pot + (size_t)b * Tlen * Ktag + j;
        const int L = slen[b];

        float alpha = __ldg(p);

        for (int t = 1; t < L; ++t) {
            const float pc = __ldg(p + t * Ktag);

            float m = alpha;
#pragma unroll
            for (int off = 16; off; off >>= 1)
                m = fmaxf(m, __shfl_xor_sync(FULLMASK, m, off));

            const float e = __expf(alpha - m);

            float a0 = 0.f, a1 = 0.f, a2 = 0.f, a3 = 0.f;
#pragma unroll
            for (int i = 0; i < 32; i += 4) {
                a0 = fmaf(__shfl_sync(FULLMASK, e, i + 0), Ecol[i + 0], a0);
                a1 = fmaf(__shfl_sync(FULLMASK, e, i + 1), Ecol[i + 1], a1);
                a2 = fmaf(__shfl_sync(FULLMASK, e, i + 2), Ecol[i + 2], a2);
                a3 = fmaf(__shfl_sync(FULLMASK, e, i + 3), Ecol[i + 3], a3);
            }
            alpha = pc + m + __logf((a0 + a1) + (a2 + a3));
        }

        // final logsumexp over alpha
        float m = alpha;
#pragma unroll
        for (int off = 16; off; off >>= 1)
            m = fmaxf(m, __shfl_xor_sync(FULLMASK, m, off));
        float e = __expf(alpha - m);
#pragma unroll
        for (int off = 16; off; off >>= 1)
            e += __shfl_xor_sync(FULLMASK, e, off);
        if (j == 0) g_logNorm[b] = m + __logf(e);
    }
}

// ---------------------------------------------------------------------------
// Kernel 2: backtrace + sequence score + log-likelihood. One warp per batch.
// ---------------------------------------------------------------------------
__global__ __launch_bounds__(128)
void crf_epilogue(const float* __restrict__ pot,
                  const float* __restrict__ trans,
                  const int*   __restrict__ slen,
                  const int*   __restrict__ tg_in,
                  float*       __restrict__ out)
{
    const int warp = (blockIdx.x * blockDim.x + threadIdx.x) >> 5;
    const int j    = threadIdx.x & 31;
    if (warp >= Bsz) return;
    const int b = warp;

    const int L  = slen[b];
    const int lt = g_lastTag[b];
    float* tagOut = out + (size_t)b * Tlen;

    // tags[t] = last_tag for t in [L-1, T-1]
    for (int t = L - 1 + j; t < Tlen; t += 32)
        tagOut[t] = (float)lt;

    // Backtrace. Chunk loads are tag-independent -> prefetchable.
    int tag = lt;
    const int cstart = (L - 1) >> 2;
    uint32_t wnext = g_bp[cstart * (Bsz * Ktag) + b * Ktag + j];
    for (int c = cstart; c >= 0; --c) {
        const uint32_t w = wnext;
        if (c > 0) wnext = g_bp[(c - 1) * (Bsz * Ktag) + b * Ktag + j];
        const int tmax = min(4 * c + 3, L - 1);
        const int tmin = max(4 * c, 1);
        for (int t = tmax; t >= tmin; --t) {
            const uint32_t wt = __shfl_sync(FULLMASK, w, tag);
            tag = (int)((wt >> ((t & 3) * 8)) & 0xFFu);
            if (j == 0) tagOut[t - 1] = (float)tag;
        }
    }

    // Sequence score
    const int*   tg = tg_in + (size_t)b * Tlen;
    const float* p  = pot + (size_t)b * Tlen * Ktag;
    float s = 0.f;
    for (int t = j; t < L; t += 32) {
        const int tt = tg[t];
        s += __ldg(&p[t * Ktag + tt]);
        if (t < L - 1) s += __ldg(&trans[tt * 32 + tg[t + 1]]);
    }
#pragma unroll
    for (int off = 16; off; off >>= 1)
        s += __shfl_xor_sync(FULLMASK, s, off);
    if (j == 0)
        out[(size_t)Bsz * Tlen + Bsz + b] = s - g_logNorm[b];
}

// ---------------------------------------------------------------------------
extern "C" void kernel_launch(void* const* d_in, const int* in_sizes, int n_in,
                              void* d_out, int out_size)
{
    const float* pot   = (const float*)d_in[0];
    const float* trans = (const float*)d_in[1];
    const int*   slen  = (const int*)d_in[2];
    const int*   tags  = (const int*)d_in[3];
    float*       out   = (float*)d_out;

    // 4096 warps (2048 viterbi + 2048 lse) -> 1024 blocks x 128 threads
    crf_forward<<<(2 * Bsz * 32) / 128, 128>>>(pot, trans, slen, out);
    // 2048 warps -> 512 blocks x 128 threads
    crf_epilogue<<<(Bsz * 32) / 128, 128>>>(pot, trans, slen, tags, out);
}

// round 3
// speedup vs baseline: 1.0257x; 1.0257x over previous
#include <cuda_runtime.h>
#include <cstdint>

#define Bsz 2048
#define Tlen 512
#define Ktag 32
#define FULLMASK 0xFFFFFFFFu

// Backpointers packed 4 timesteps per uint32 (bp fits in a byte).
// Layout: g_bp[(t>>2) * (B*K) + b*K + j] -> coalesced 128B per-warp accesses.
__device__ uint32_t g_bp[(Tlen / 4) * Bsz * Ktag];   // ~33.5 MB, L2-resident

// ---------------------------------------------------------------------------
// One kernel. Warp w < B  -> Viterbi forward + backtrace + tag output + score.
//            Warp w >= B  -> logsumexp forward + sequence score + loglik.
// One warp per batch element; lane j owns tag j.
// Alpha/e broadcast via smem double buffer (uniform-address LDS.128, N=1).
// ---------------------------------------------------------------------------
__global__ __launch_bounds__(128, 7)
void crf_fused(const float* __restrict__ pot,
               const float* __restrict__ trans,
               const int*   __restrict__ slen,
               const int*   __restrict__ tg_in,
               float*       __restrict__ out)
{
    __shared__ float buf[4][2][32];           // [warp-in-block][double][lane]
    const int warp  = (blockIdx.x * blockDim.x + threadIdx.x) >> 5;
    const int wi    = (threadIdx.x >> 5) & 3;
    const int j     = threadIdx.x & 31;

    if (warp < Bsz) {
        // ============================ VITERBI ============================
        const int b = warp;
        float Tcol[32];
#pragma unroll
        for (int i = 0; i < 32; ++i) Tcol[i] = __ldg(&trans[i * 32 + j]);

        const float* p = pot + (size_t)b * Tlen * Ktag + j;
        const int L = slen[b];

        float alpha = __ldg(p);          // t = 0
        uint32_t bpw = 0;

#pragma unroll 4
        for (int t = 1; t < L; ++t) {
            const float pc = __ldg(p + t * Ktag);     // prefetch early

            buf[wi][t & 1][j] = alpha;
            __syncwarp();
            const float4* A = (const float4*)buf[wi][t & 1];

            // 4 chains by (i mod 4); strict > keeps earliest within chain.
            float bv0 = -3.4e38f, bv1 = -3.4e38f, bv2 = -3.4e38f, bv3 = -3.4e38f;
            int   bi0 = 0, bi1 = 1, bi2 = 2, bi3 = 3;
#pragma unroll
            for (int g = 0; g < 8; ++g) {
                const float4 a = A[g];
                float s;
                s = a.x + Tcol[4 * g + 0]; if (s > bv0) { bv0 = s; bi0 = 4 * g + 0; }
                s = a.y + Tcol[4 * g + 1]; if (s > bv1) { bv1 = s; bi1 = 4 * g + 1; }
                s = a.z + Tcol[4 * g + 2]; if (s > bv2) { bv2 = s; bi2 = 4 * g + 2; }
                s = a.w + Tcol[4 * g + 3]; if (s > bv3) { bv3 = s; bi3 = 4 * g + 3; }
            }
            // index-aware merges: exact first-argmax semantics
            if (bv1 > bv0 || (bv1 == bv0 && bi1 < bi0)) { bv0 = bv1; bi0 = bi1; }
            if (bv2 > bv0 || (bv2 == bv0 && bi2 < bi0)) { bv0 = bv2; bi0 = bi2; }
            if (bv3 > bv0 || (bv3 == bv0 && bi3 < bi0)) { bv0 = bv3; bi0 = bi3; }

            alpha = pc + bv0;
            bpw |= (uint32_t)bi0 << ((t & 3) * 8);
            if ((t & 3) == 3) {
                g_bp[(t >> 2) * (Bsz * Ktag) + b * Ktag + j] = bpw;
                bpw = 0;
            }
        }
        if (L >= 2 && ((L - 1) & 3) != 3)
            g_bp[((L - 1) >> 2) * (Bsz * Ktag) + b * Ktag + j] = bpw;

        // final max/argmax over alpha (first-max semantics), result in all lanes
        float v = alpha;
        int idx = j;
#pragma unroll
        for (int off = 16; off; off >>= 1) {
            float vv = __shfl_xor_sync(FULLMASK, v, off);
            int   ii = __shfl_xor_sync(FULLMASK, idx, off);
            if (vv > v || (vv == v && ii < idx)) { v = vv; idx = ii; }
        }
        if (j == 0) out[(size_t)Bsz * Tlen + b] = v;   // best_score

        // ------------------- backtrace + tag output -------------------
        float* tagOut = out + (size_t)b * Tlen;
        for (int t = L - 1 + j; t < Tlen; t += 32)
            tagOut[t] = (float)idx;                    // tail = last tag

        if (L >= 2) {
            int tag = idx;
            float myTag = 0.f;
            const int cstart = (L - 1) >> 2;
            uint32_t w0 = g_bp[cstart * (Bsz * Ktag) + b * Ktag + j];
            uint32_t w1 = (cstart >= 1) ? g_bp[(cstart - 1) * (Bsz * Ktag) + b * Ktag + j] : 0u;
            for (int c = cstart; c >= 0; --c) {
                const uint32_t wc = w0;
                w0 = w1;
                w1 = (c >= 2) ? g_bp[(c - 2) * (Bsz * Ktag) + b * Ktag + j] : 0u;
                const int tmax = min(4 * c + 3, L - 1);
                const int tmin = max(4 * c, 1);
                for (int t = tmax; t >= tmin; --t) {
                    const uint32_t wt = __shfl_sync(FULLMASK, wc, tag);
                    tag = (int)((wt >> ((t & 3) * 8)) & 0xFFu);
                    const int pos = t - 1;             // tag for position t-1
                    if ((pos & 31) == j) myTag = (float)tag;
                    if ((pos & 31) == 0) {             // flush coalesced window
                        if (pos + j <= L - 2) tagOut[pos + j] = myTag;
                    }
                }
            }
        }
    } else if (warp < 2 * Bsz) {
        // ========================== LOGSUMEXP ==========================
        const int b = warp - Bsz;
        float Ecol[32];
#pragma unroll
        for (int i = 0; i < 32; ++i) Ecol[i] = expf(__ldg(&trans[i * 32 + j]));

        const float* p = pot + (size_t)b * Tlen * Ktag + j;
        const int L = slen[b];

        float alpha = __ldg(p);

#pragma unroll 2
        for (int t = 1; t < L; ++t) {
            const float pc = __ldg(p + t * Ktag);

            // shift by lane0's alpha: intra-step spread is bounded (~12),
            // so exp() stays well inside fp32 range.
            const float m = __shfl_sync(FULLMASK, alpha, 0);
            const float e = __expf(alpha - m);

            buf[wi][t & 1][j] = e;
            __syncwarp();
            const float4* A = (const float4*)buf[wi][t & 1];

            float a0 = 0.f, a1 = 0.f, a2 = 0.f, a3 = 0.f;
#pragma unroll
            for (int g = 0; g < 8; ++g) {
                const float4 a = A[g];
                a0 = fmaf(a.x, Ecol[4 * g + 0], a0);
                a1 = fmaf(a.y, Ecol[4 * g + 1], a1);
                a2 = fmaf(a.z, Ecol[4 * g + 2], a2);
                a3 = fmaf(a.w, Ecol[4 * g + 3], a3);
            }
            alpha = pc + m + __logf((a0 + a1) + (a2 + a3));
        }

        // final logsumexp over lanes
        float mm = alpha;
#pragma unroll
        for (int off = 16; off; off >>= 1)
            mm = fmaxf(mm, __shfl_xor_sync(FULLMASK, mm, off));
        float e = __expf(alpha - mm);
#pragma unroll
        for (int off = 16; off; off >>= 1)
            e += __shfl_xor_sync(FULLMASK, e, off);
        const float logNorm = mm + __logf(e);

        // ------------------ sequence score + loglik ------------------
        const int*   tg = tg_in + (size_t)b * Tlen;
        const float* p0 = pot + (size_t)b * Tlen * Ktag;
        float s = 0.f;
        for (int t = j; t < L; t += 32) {
            const int tt = tg[t];
            s += __ldg(&p0[t * Ktag + tt]);
            if (t < L - 1) s += __ldg(&trans[tt * 32 + tg[t + 1]]);
        }
#pragma unroll
        for (int off = 16; off; off >>= 1)
            s += __shfl_xor_sync(FULLMASK, s, off);
        if (j == 0)
            out[(size_t)Bsz * Tlen + Bsz + b] = s - logNorm;
    }
}

// ---------------------------------------------------------------------------
extern "C" void kernel_launch(void* const* d_in, const int* in_sizes, int n_in,
                              void* d_out, int out_size)
{
    const float* pot   = (const float*)d_in[0];
    const float* trans = (const float*)d_in[1];
    const int*   slen  = (const int*)d_in[2];
    const int*   tags  = (const int*)d_in[3];
    float*       out   = (float*)d_out;

    // 4096 warps (2048 viterbi + 2048 lse) -> 1024 blocks x 128 threads
    crf_fused<<<(2 * Bsz * 32) / 128, 128>>>(pot, trans, slen, tags, out);
}

// round 4
// speedup vs baseline: 1.6457x; 1.6045x over previous
#include <cuda_runtime.h>
#include <cstdint>

#define Bsz 2048
#define Tlen 512
#define Ktag 32
#define FULLMASK 0xFFFFFFFFu
#define STRIDE (Bsz * Ktag)

// Per-step alpha rows (exact), recomputed-argmax backtrace reads these.
__device__ float g_alpha[(size_t)Tlen * Bsz * Ktag];   // 134 MB
__device__ int   g_perm[Bsz];                          // length-sorted batch order

union f2u { float2 f; unsigned long long u; };

__device__ __forceinline__ unsigned long long add2(unsigned long long a, unsigned long long b) {
    unsigned long long r; asm("add.rn.f32x2 %0,%1,%2;" : "=l"(r) : "l"(a), "l"(b)); return r;
}
__device__ __forceinline__ unsigned long long pfma2(unsigned long long a, unsigned long long b, unsigned long long c) {
    unsigned long long r; asm("fma.rn.f32x2 %0,%1,%2,%3;" : "=l"(r) : "l"(a), "l"(b), "l"(c)); return r;
}
// order-preserving float->uint bijection (no NaNs in this problem)
__device__ __forceinline__ unsigned ordf(float s) {
    int b = __float_as_int(s);
    return (unsigned)(b ^ ((b >> 31) | 0x80000000));
}

// ---------------------------------------------------------------------------
// Kernel 0: bitonic sort of (L<<11 | b) -> g_perm. One block, 1024 threads.
// ---------------------------------------------------------------------------
__global__ void crf_sort(const int* __restrict__ slen)
{
    __shared__ unsigned key[Bsz];
    const int tid = threadIdx.x;
    for (int i = tid; i < Bsz; i += 1024)
        key[i] = ((unsigned)slen[i] << 11) | (unsigned)i;
    __syncthreads();
    for (int k = 2; k <= Bsz; k <<= 1) {
        for (int jj = k >> 1; jj > 0; jj >>= 1) {
            for (int i = tid; i < Bsz; i += 1024) {
                int l = i ^ jj;
                if (l > i) {
                    unsigned a = key[i], c = key[l];
                    bool asc = ((i & k) == 0);
                    if ((a > c) == asc) { key[i] = c; key[l] = a; }
                }
            }
            __syncthreads();
        }
    }
    for (int i = tid; i < Bsz; i += 1024)
        g_perm[i] = (int)(key[i] & 0x7FFu);
}

// ---------------------------------------------------------------------------
// Kernel 1: one warp per block (32 thr). Block w < 1024 -> Viterbi on batches
// perm[w], perm[2047-w] (length-balanced pair). Block w >= 1024 -> logsumexp +
// score on the same pairing. Lane j owns tag column j.
// ---------------------------------------------------------------------------
__global__ __launch_bounds__(32)
void crf_main(const float* __restrict__ pot,
              const float* __restrict__ trans,
              const int*   __restrict__ slen,
              const int*   __restrict__ tg_in,
              float*       __restrict__ out)
{
    __shared__ __align__(16) float buf[2][32];
    __shared__ float transS[32 * 33];               // [i][tag], pad 33: conflict-free
    const int w = blockIdx.x;
    const int j = threadIdx.x;

    if (w < Bsz / 2) {
        // ============================ VITERBI ============================
        f2u Tp[16];                                  // packed rows (2q, 2q+1), col j
#pragma unroll
        for (int q = 0; q < 16; ++q) {
            Tp[q].f.x = __ldg(&trans[(2 * q) * 32 + j]);
            Tp[q].f.y = __ldg(&trans[(2 * q + 1) * 32 + j]);
        }
        for (int q = j; q < 32 * 32; q += 32)       // transS[i*33 + c] = T[i][c]
            transS[(q >> 5) * 33 + (q & 31)] = __ldg(&trans[q]);
        __syncwarp();

#pragma unroll 1
        for (int task = 0; task < 2; ++task) {
            const int b = g_perm[task ? (Bsz - 1 - w) : w];
            const int L = slen[b];
            const float* p = pot + (size_t)b * Tlen * Ktag + j;
            float* aSt = g_alpha + (size_t)b * Ktag + j;

            float alpha = __ldg(p);                  // t = 0
#pragma unroll 2
            for (int t = 1; t < L; ++t) {
                const float pc = __ldg(p + t * Ktag);
                buf[t & 1][j] = alpha;
                aSt[(size_t)(t - 1) * STRIDE] = alpha;   // save for backtrace
                __syncwarp();
                const ulonglong2* A = (const ulonglong2*)buf[t & 1];
                float m0 = -3.4e38f, m1 = -3.4e38f, m2 = -3.4e38f, m3 = -3.4e38f;
#pragma unroll
                for (int g = 0; g < 8; ++g) {
                    const ulonglong2 av = A[g];
                    f2u s0, s1;
                    s0.u = add2(av.x, Tp[2 * g].u);
                    s1.u = add2(av.y, Tp[2 * g + 1].u);
                    m0 = fmaxf(m0, s0.f.x);
                    m1 = fmaxf(m1, s0.f.y);
                    m2 = fmaxf(m2, s1.f.x);
                    m3 = fmaxf(m3, s1.f.y);
                }
                alpha = pc + fmaxf(fmaxf(m0, m1), fmaxf(m2, m3));
            }

            // final max/argmax (first-max) via redux + ballot
            const unsigned ua = ordf(alpha);
            const unsigned um = __reduce_max_sync(FULLMASK, ua);
            const int idx = __ffs((int)__ballot_sync(FULLMASK, ua == um)) - 1;
            const float v = __shfl_sync(FULLMASK, alpha, idx);
            if (j == 0) out[(size_t)Bsz * Tlen + b] = v;     // best_score

            float* tagOut = out + (size_t)b * Tlen;
            for (int t = L - 1 + j; t < Tlen; t += 32)
                tagOut[t] = (float)idx;                      // tail = last tag

            // ---------- backtrace: recompute argmax from stored alphas ----------
            if (L >= 2) {
                int tag = idx;
                float myTag = 0.f;
                float cur[8], nxt[8];
                const int t0 = L - 1;
#pragma unroll
                for (int k = 0; k < 8; ++k) {
                    const int tt = t0 - k;
                    cur[k] = (tt >= 1) ? aSt[(size_t)(tt - 1) * STRIDE] : 0.f;
                }
                for (int tc = t0; tc >= 1; tc -= 8) {
#pragma unroll
                    for (int k = 0; k < 8; ++k) {            // prefetch next chunk
                        const int tt = tc - 8 - k;
                        nxt[k] = (tt >= 1) ? aSt[(size_t)(tt - 1) * STRIDE] : 0.f;
                    }
#pragma unroll
                    for (int k = 0; k < 8; ++k) {
                        const int tt = tc - k;
                        if (tt >= 1) {
                            const float s = cur[k] + transS[j * 33 + tag];
                            const unsigned u = ordf(s);
                            const unsigned mm = __reduce_max_sync(FULLMASK, u);
                            const int prev = __ffs((int)__ballot_sync(FULLMASK, u == mm)) - 1;
                            const int pos = tt - 1;
                            if ((pos & 31) == j) myTag = (float)prev;
                            if ((pos & 31) == 0 && pos + j <= L - 2)
                                tagOut[pos + j] = myTag;     // coalesced flush
                            tag = prev;
                        }
                    }
#pragma unroll
                    for (int k = 0; k < 8; ++k) cur[k] = nxt[k];
                }
            }
        }
    } else {
        // ========================== LOGSUMEXP + SCORE ==========================
        const int w2 = w - Bsz / 2;
        f2u Ep[16];
#pragma unroll
        for (int q = 0; q < 16; ++q) {
            Ep[q].f.x = expf(__ldg(&trans[(2 * q) * 32 + j]));
            Ep[q].f.y = expf(__ldg(&trans[(2 * q + 1) * 32 + j]));
        }

#pragma unroll 1
        for (int task = 0; task < 2; ++task) {
            const int b = g_perm[task ? (Bsz - 1 - w2) : w2];
            const int L = slen[b];
            const float* p = pot + (size_t)b * Tlen * Ktag + j;

            float alpha = __ldg(p);
#pragma unroll 2
            for (int t = 1; t < L; ++t) {
                const float pc = __ldg(p + t * Ktag);
                // shift by lane0 alpha: intra-step spread bounded, fp32-safe
                const float m = __shfl_sync(FULLMASK, alpha, 0);
                const float e = __expf(alpha - m);
                buf[t & 1][j] = e;
                __syncwarp();
                const ulonglong2* A = (const ulonglong2*)buf[t & 1];
                f2u a0, a1; a0.u = 0ull; a1.u = 0ull;
#pragma unroll
                for (int g = 0; g < 8; ++g) {
                    const ulonglong2 av = A[g];
                    a0.u = pfma2(av.x, Ep[2 * g].u, a0.u);
                    a1.u = pfma2(av.y, Ep[2 * g + 1].u, a1.u);
                }
                a0.u = add2(a0.u, a1.u);
                alpha = pc + m + __logf(a0.f.x + a0.f.y);
            }

            // final logsumexp over lanes
            float mm = alpha;
#pragma unroll
            for (int off = 16; off; off >>= 1)
                mm = fmaxf(mm, __shfl_xor_sync(FULLMASK, mm, off));
            float e = __expf(alpha - mm);
#pragma unroll
            for (int off = 16; off; off >>= 1)
                e += __shfl_xor_sync(FULLMASK, e, off);
            const float logNorm = mm + __logf(e);

            // sequence score + log-likelihood
            const int*   tg = tg_in + (size_t)b * Tlen;
            const float* p0 = pot + (size_t)b * Tlen * Ktag;
            float s = 0.f;
            for (int t = j; t < L; t += 32) {
                const int tt = tg[t];
                s += __ldg(&p0[t * Ktag + tt]);
                if (t < L - 1) s += __ldg(&trans[tt * 32 + tg[t + 1]]);
            }
#pragma unroll
            for (int off = 16; off; off >>= 1)
                s += __shfl_xor_sync(FULLMASK, s, off);
            if (j == 0)
                out[(size_t)Bsz * Tlen + Bsz + b] = s - logNorm;
        }
    }
}

// ---------------------------------------------------------------------------
extern "C" void kernel_launch(void* const* d_in, const int* in_sizes, int n_in,
                              void* d_out, int out_size)
{
    const float* pot   = (const float*)d_in[0];
    const float* trans = (const float*)d_in[1];
    const int*   slen  = (const int*)d_in[2];
    const int*   tags  = (const int*)d_in[3];
    float*       out   = (float*)d_out;

    crf_sort<<<1, 1024>>>(slen);
    crf_main<<<Bsz, 32>>>(pot, trans, slen, tags, out);
}

// round 5
// speedup vs baseline: 2.4004x; 1.4586x over previous
#include <cuda_runtime.h>
#include <cstdint>

#define Bsz 2048
#define Tlen 512
#define Ktag 32
#define FULLMASK 0xFFFFFFFFu
#define STRIDE (Bsz * Ktag)

// Per-step alpha rows (exact), recomputed-argmax backtrace reads these.
__device__ float g_alpha[(size_t)Tlen * Bsz * Ktag];   // 134 MB
__device__ int   g_perm[Bsz];                          // length-sorted batch order

union f2u { float2 f; unsigned long long u; };

__device__ __forceinline__ unsigned long long add2(unsigned long long a, unsigned long long b) {
    unsigned long long r; asm("add.rn.f32x2 %0,%1,%2;" : "=l"(r) : "l"(a), "l"(b)); return r;
}
__device__ __forceinline__ unsigned long long pfma2(unsigned long long a, unsigned long long b, unsigned long long c) {
    unsigned long long r; asm("fma.rn.f32x2 %0,%1,%2,%3;" : "=l"(r) : "l"(a), "l"(b), "l"(c)); return r;
}
// order-preserving float->uint bijection (no NaNs in this problem)
__device__ __forceinline__ unsigned ordf(float s) {
    int b = __float_as_int(s);
    return (unsigned)(b ^ ((b >> 31) | 0x80000000));
}

// ---------------------------------------------------------------------------
// Kernel 0: counting sort by length -> g_perm. One block, 1024 threads.
// Lengths in [1,512] -> 512 bins. In-bin order is irrelevant (balancing only).
// ---------------------------------------------------------------------------
__global__ void crf_sort(const int* __restrict__ slen)
{
    __shared__ int hist[512];
    __shared__ int wsum[16];
    const int tid  = threadIdx.x;
    const int lane = tid & 31, wid = tid >> 5;

    for (int i = tid; i < 512; i += 1024) hist[i] = 0;
    __syncthreads();
    for (int b = tid; b < Bsz; b += 1024) atomicAdd(&hist[slen[b] - 1], 1);
    __syncthreads();

    int v = 0, s = 0;
    if (tid < 512) {
        v = hist[tid];
        s = v;
#pragma unroll
        for (int off = 1; off < 32; off <<= 1) {
            int u = __shfl_up_sync(FULLMASK, s, off);
            if (lane >= off) s += u;
        }
        if (lane == 31) wsum[wid] = s;      // warp totals
    }
    __syncthreads();
    if (tid < 16) {                          // exclusive scan of 16 warp totals
        int t = wsum[tid], ss = t;
#pragma unroll
        for (int off = 1; off < 16; off <<= 1) {
            int u = __shfl_up_sync(0xFFFFu, ss, off);
            if (tid >= off) ss += u;
        }
        wsum[tid] = ss - t;
    }
    __syncthreads();
    if (tid < 512) hist[tid] = (s - v) + wsum[wid];   // exclusive bin base
    __syncthreads();
    for (int b = tid; b < Bsz; b += 1024) {
        int pos = atomicAdd(&hist[slen[b] - 1], 1);
        g_perm[pos] = b;
    }
}

// ---------------------------------------------------------------------------
// Kernel 1: one warp per block. Block w < 1024 -> Viterbi on batches perm[w],
// perm[2047-w] (length-balanced pair). Block w >= 1024 -> logsumexp + score on
// the same pairing. Lane j owns tag column j. Potentials are prefetched 8
// steps ahead through a named-register ring (DRAM latency ~577cyc hidden).
// ---------------------------------------------------------------------------
__global__ __launch_bounds__(32)
void crf_main(const float* __restrict__ pot,
              const float* __restrict__ trans,
              const int*   __restrict__ slen,
              const int*   __restrict__ tg_in,
              float*       __restrict__ out)
{
    __shared__ __align__(16) float buf[2][32];
    __shared__ float transS[32 * 33];               // [i][tag], pad 33: conflict-free
    const int w = blockIdx.x;
    const int j = threadIdx.x;

    if (w < Bsz / 2) {
        // ============================ VITERBI ============================
        f2u Tp[16];                                  // packed rows (2q,2q+1), col j
#pragma unroll
        for (int q = 0; q < 16; ++q) {
            Tp[q].f.x = __ldg(&trans[(2 * q) * 32 + j]);
            Tp[q].f.y = __ldg(&trans[(2 * q + 1) * 32 + j]);
        }
        for (int q = j; q < 32 * 32; q += 32)       // transS[i*33+c] = T[i][c]
            transS[(q >> 5) * 33 + (q & 31)] = __ldg(&trans[q]);
        __syncwarp();

#pragma unroll 1
        for (int task = 0; task < 2; ++task) {
            const int b = g_perm[task ? (Bsz - 1 - w) : w];
            const int L = slen[b];
            const float* p = pot + (size_t)b * Tlen * Ktag + j;
            float* aSt = g_alpha + (size_t)b * Ktag + j;

            float alpha = __ldg(p);                  // t = 0

            auto LD = [&](int t) -> float {          // clamped prefetch load
                return __ldg(p + (size_t)min(t, L - 1) * Ktag);
            };
            auto step = [&](float pcv, int t) {
                buf[t & 1][j] = alpha;
                aSt[(size_t)(t - 1) * STRIDE] = alpha;   // save for backtrace
                __syncwarp();
                const ulonglong2* A = (const ulonglong2*)buf[t & 1];
                float m0 = -3.4e38f, m1 = -3.4e38f, m2 = -3.4e38f, m3 = -3.4e38f;
#pragma unroll
                for (int g = 0; g < 8; ++g) {
                    const ulonglong2 av = A[g];
                    f2u s0, s1;
                    s0.u = add2(av.x, Tp[2 * g].u);
                    s1.u = add2(av.y, Tp[2 * g + 1].u);
                    m0 = fmaxf(m0, s0.f.x);
                    m1 = fmaxf(m1, s0.f.y);
                    m2 = fmaxf(m2, s1.f.x);
                    m3 = fmaxf(m3, s1.f.y);
                }
                alpha = pcv + fmaxf(fmaxf(m0, m1), fmaxf(m2, m3));
            };

            float q0 = LD(1), q1 = LD(2), q2 = LD(3), q3 = LD(4),
                  q4 = LD(5), q5 = LD(6), q6 = LD(7), q7 = LD(8);
            int t = 1;
#pragma unroll 1
            for (; t + 8 <= L; t += 8) {
                step(q0, t + 0); q0 = LD(t + 8);
                step(q1, t + 1); q1 = LD(t + 9);
                step(q2, t + 2); q2 = LD(t + 10);
                step(q3, t + 3); q3 = LD(t + 11);
                step(q4, t + 4); q4 = LD(t + 12);
                step(q5, t + 5); q5 = LD(t + 13);
                step(q6, t + 6); q6 = LD(t + 14);
                step(q7, t + 7); q7 = LD(t + 15);
            }
#pragma unroll 1
            for (; t < L; ++t) step(__ldg(p + (size_t)t * Ktag), t);

            // final max/argmax (first-max) via redux + ballot
            const unsigned ua = ordf(alpha);
            const unsigned um = __reduce_max_sync(FULLMASK, ua);
            const int idx = __ffs((int)__ballot_sync(FULLMASK, ua == um)) - 1;
            const float v = __shfl_sync(FULLMASK, alpha, idx);
            if (j == 0) out[(size_t)Bsz * Tlen + b] = v;     // best_score

            float* tagOut = out + (size_t)b * Tlen;
            for (int tt = L - 1 + j; tt < Tlen; tt += 32)
                tagOut[tt] = (float)idx;                     // tail = last tag

            // ---------- backtrace: recompute argmax from stored alphas ----------
            if (L >= 2) {
                int tag = idx;
                float myTag = 0.f;
                float cur[8], nxt[8];
                const int t0 = L - 1;
#pragma unroll
                for (int k = 0; k < 8; ++k) {
                    const int tt = t0 - k;
                    cur[k] = (tt >= 1) ? aSt[(size_t)(tt - 1) * STRIDE] : 0.f;
                }
#pragma unroll 1
                for (int tc = t0; tc >= 1; tc -= 8) {
#pragma unroll
                    for (int k = 0; k < 8; ++k) {            // prefetch next chunk
                        const int tt = tc - 8 - k;
                        nxt[k] = (tt >= 1) ? aSt[(size_t)(tt - 1) * STRIDE] : 0.f;
                    }
#pragma unroll
                    for (int k = 0; k < 8; ++k) {
                        const int tt = tc - k;
                        if (tt >= 1) {
                            const float s = cur[k] + transS[j * 33 + tag];
                            const unsigned u = ordf(s);
                            const unsigned mm = __reduce_max_sync(FULLMASK, u);
                            const int prev = __ffs((int)__ballot_sync(FULLMASK, u == mm)) - 1;
                            const int pos = tt - 1;
                            if ((pos & 31) == j) myTag = (float)prev;
                            if ((pos & 31) == 0 && pos + j <= L - 2)
                                tagOut[pos + j] = myTag;     // coalesced flush
                            tag = prev;
                        }
                    }
#pragma unroll
                    for (int k = 0; k < 8; ++k) cur[k] = nxt[k];
                }
            }
        }
    } else {
        // ========================== LOGSUMEXP + SCORE ==========================
        const int w2 = w - Bsz / 2;
        f2u Ep[16];
#pragma unroll
        for (int q = 0; q < 16; ++q) {
            Ep[q].f.x = expf(__ldg(&trans[(2 * q) * 32 + j]));
            Ep[q].f.y = expf(__ldg(&trans[(2 * q + 1) * 32 + j]));
        }

#pragma unroll 1
        for (int task = 0; task < 2; ++task) {
            const int b = g_perm[task ? (Bsz - 1 - w2) : w2];
            const int L = slen[b];
            const float* p = pot + (size_t)b * Tlen * Ktag + j;

            float alpha = __ldg(p);

            auto LD = [&](int t) -> float {
                return __ldg(p + (size_t)min(t, L - 1) * Ktag);
            };
            auto step = [&](float pcv, int t) {
                // shift by lane0 alpha: intra-step spread bounded, fp32-safe
                const float m = __shfl_sync(FULLMASK, alpha, 0);
                const float e = __expf(alpha - m);
                buf[t & 1][j] = e;
                __syncwarp();
                const ulonglong2* A = (const ulonglong2*)buf[t & 1];
                f2u a0, a1; a0.u = 0ull; a1.u = 0ull;
#pragma unroll
                for (int g = 0; g < 8; ++g) {
                    const ulonglong2 av = A[g];
                    a0.u = pfma2(av.x, Ep[2 * g].u, a0.u);
                    a1.u = pfma2(av.y, Ep[2 * g + 1].u, a1.u);
                }
                a0.u = add2(a0.u, a1.u);
                alpha = pcv + m + __logf(a0.f.x + a0.f.y);
            };

            float q0 = LD(1), q1 = LD(2), q2 = LD(3), q3 = LD(4),
                  q4 = LD(5), q5 = LD(6), q6 = LD(7), q7 = LD(8);
            int t = 1;
#pragma unroll 1
            for (; t + 8 <= L; t += 8) {
                step(q0, t + 0); q0 = LD(t + 8);
                step(q1, t + 1); q1 = LD(t + 9);
                step(q2, t + 2); q2 = LD(t + 10);
                step(q3, t + 3); q3 = LD(t + 11);
                step(q4, t + 4); q4 = LD(t + 12);
                step(q5, t + 5); q5 = LD(t + 13);
                step(q6, t + 6); q6 = LD(t + 14);
                step(q7, t + 7); q7 = LD(t + 15);
            }
#pragma unroll 1
            for (; t < L; ++t) step(__ldg(p + (size_t)t * Ktag), t);

            // final logsumexp over lanes
            float mm = alpha;
#pragma unroll
            for (int off = 16; off; off >>= 1)
                mm = fmaxf(mm, __shfl_xor_sync(FULLMASK, mm, off));
            float e = __expf(alpha - mm);
#pragma unroll
            for (int off = 16; off; off >>= 1)
                e += __shfl_xor_sync(FULLMASK, e, off);
            const float logNorm = mm + __logf(e);

            // sequence score + log-likelihood
            const int*   tg = tg_in + (size_t)b * Tlen;
            const float* p0 = pot + (size_t)b * Tlen * Ktag;
            float s = 0.f;
            for (int t2 = j; t2 < L; t2 += 32) {
                const int tt = tg[t2];
                s += __ldg(&p0[t2 * Ktag + tt]);
                if (t2 < L - 1) s += __ldg(&trans[tt * 32 + tg[t2 + 1]]);
            }
#pragma unroll
            for (int off = 16; off; off >>= 1)
                s += __shfl_xor_sync(FULLMASK, s, off);
            if (j == 0)
                out[(size_t)Bsz * Tlen + Bsz + b] = s - logNorm;
        }
    }
}

// ---------------------------------------------------------------------------
extern "C" void kernel_launch(void* const* d_in, const int* in_sizes, int n_in,
                              void* d_out, int out_size)
{
    const float* pot   = (const float*)d_in[0];
    const float* trans = (const float*)d_in[1];
    const int*   slen  = (const int*)d_in[2];
    const int*   tags  = (const int*)d_in[3];
    float*       out   = (float*)d_out;

    crf_sort<<<1, 1024>>>(slen);
    crf_main<<<Bsz, 32>>>(pot, trans, slen, tags, out);
}